// round 13
// baseline (speedup 1.0000x reference)
#include <cuda_runtime.h>
#include <cstddef>
#include <cstdint>

// CTC loss forward. B=32, T=800, C=5000, L=100, S=201.
//
// R12: single merged kernel = 32 alpha CTAs (bids 0..31, wave-1 resident) +
// 3200 gather CTAs (one per (8-row chunk, batch), chunk-major). Gather's
// irreducible ~36us of DRAM time (243MB of 128B-line fetches) now runs UNDER
// the recursion instead of before it. Producer->consumer pacing via
// per-(b,chunk) flags: st.release.gpu on publish, software-pipelined
// ld.acquire.gpu on consume (value branched on one group later -> no
// critical-path cost when already set). Alpha body identical to R11
// (two-steps-per-barrier pairs; 82.6us standalone). Tiny reset kernel
// clears flags each graph replay.

#define Bb 32
#define Tt 800
#define Cc 5000
#define Ll 100
#define EP 128            // emit row stride (floats), line-aligned
#define NEGV (-1e30f)
#define LOG2E 1.4426950408889634f
#define LN2   0.6931471805599453f
#define DP 4              // prefetch depth in PAIRS (8 time steps)
#define NTHR 128
#define CH 8              // rows per gather chunk (== 2*DP rows per group)
#define NCHUNK (Tt / CH)  // 100
#define NGATHER (NCHUNK * Bb)

__device__ float    g_emit[(size_t)Bb * Tt * EP];
__device__ float    g_tot[Bb];
__device__ unsigned g_done;              // self-resetting
__device__ int      g_flag[NGATHER];     // reset each replay by reset_kernel

__device__ __forceinline__ float ex2f(float x) {
    float y; asm("ex2.approx.ftz.f32 %0, %1;" : "=f"(y) : "f"(x)); return y;
}
__device__ __forceinline__ float lg2f(float x) {
    float y; asm("lg2.approx.ftz.f32 %0, %1;" : "=f"(y) : "f"(x)); return y;
}
__device__ __forceinline__ int ld_acq(const int* p) {
    int v;
    asm volatile("ld.acquire.gpu.global.b32 %0, [%1];"
                 : "=r"(v) : "l"(p) : "memory");
    return v;
}
__device__ __forceinline__ void st_rel(int* p, int v) {
    asm volatile("st.release.gpu.global.b32 [%0], %1;"
                 :: "l"(p), "r"(v) : "memory");
}

// (base,sum) logaddexp combine: (bx,sx) (+) (by,sy) -> (mb, ms), single ex2.
#define LAE(bx, sx, by, sy, mb, ms)                                        \
    {                                                                      \
        float d_ = __fadd_rn(bx, -(by));                                   \
        float u_ = ex2f(fminf(d_, -d_));                                   \
        mb = fmaxf(bx, by);                                                \
        ms = (d_ >= 0.f) ? __fmaf_rn(sy, u_, sx) : __fmaf_rn(sx, u_, sy);  \
    }

// ---------------------------------------------------------------------------
__global__ void reset_kernel() {
    int i = blockIdx.x * blockDim.x + threadIdx.x;
    if (i < NGATHER) g_flag[i] = 0;
}

// ---------------------------------------------------------------------------
// Merged kernel. bid < Bb: alpha block for batch bid. bid >= Bb: gather.
// ---------------------------------------------------------------------------
__global__ __launch_bounds__(NTHR, 1)
void ctc_main(const float* __restrict__ lp,
              const int* __restrict__ targets,
              const int* __restrict__ ilen,
              const int* __restrict__ tlen,
              float* __restrict__ out)
{
    // ======================= GATHER BLOCKS =======================
    if (blockIdx.x >= Bb) {
        const int g  = blockIdx.x - Bb;
        const int ct = g >> 5;           // chunk (t/8), chunk-major order
        const int b  = g & 31;
        const int il = ilen[b];
        const int r0 = ct * CH;
        const float* __restrict__ rowp = lp + (size_t)b * Tt * Cc;
        for (int idx = threadIdx.x; idx < CH * (Ll + 1); idx += NTHR) {
            int dr = idx / (Ll + 1);
            int j  = idx - dr * (Ll + 1);
            int r  = r0 + dr;
            if (r < il) {
                int c = (j == 0) ? 0 : targets[b * Ll + (j - 1)];
                g_emit[(size_t)(b * Tt + r) * EP + j] =
                    LOG2E * __ldg(rowp + (size_t)r * Cc + c);
            }
        }
        __syncthreads();
        if (threadIdx.x == 0) st_rel(&g_flag[ct * Bb + b], 1);
        return;
    }

    // ======================= ALPHA BLOCKS ========================
    __shared__ float4 sh[2][NTHR + 2];
    __shared__ int s_lastflag;

    const int b = blockIdx.x;
    const int i = threadIdx.x;
    const int last = ilen[b] - 1;

    const int tgR   = (i < Ll)              ? targets[b * Ll + i]     : 0;
    const int tgpR  = (i >= 1 && i <= Ll)   ? targets[b * Ll + i - 1] : -1;
    const int tgppR = (i >= 2 && i <= Ll+1) ? targets[b * Ll + i - 2] : -1;
    const bool skip  = (tgR  != tgpR);
    const bool skipP = (tgpR != tgppR);
    const int jo = (i < Ll)            ? i + 1 : 0;   // own odd emission col
    const int jp = (i >= 1 && i <= Ll) ? i     : 0;   // neighbor odd col

    const float* __restrict__ em = g_emit + (size_t)b * Tt * EP;

    if (i < 2) {
        sh[0][i] = make_float4(NEGV, 0.f, NEGV, 0.f);
        sh[1][i] = make_float4(NEGV, 0.f, NEGV, 0.f);
    }

    const int ts0  = (last & 1) ? 1 : 0;
    const int maxc = last >> 3;                  // last chunk alpha reads
    // Pre-wait chunks covering rows 0 .. ts0+16 (init + rings + group 0).
    int wc = (ts0 + 16) >> 3; if (wc > maxc) wc = maxc;
    for (int c = 0; c <= wc; ++c)
        while (ld_acq(&g_flag[c * Bb + b]) == 0) {}
    int nextc = wc;                              // highest ensured chunk
    int pfc = (nextc < maxc) ? nextc + 1 : -1;   // pipelined flag chunk
    int pfv = (pfc >= 0) ? ld_acq(&g_flag[pfc * Bb + b]) : 1;

    // t=0 init (log2 domain, alpha = base + lg2(sum)); emit pre-scaled.
    float se = 1.f, so = 1.f;
    float be = (i == 0) ? em[0]  : NEGV;
    float bo = (i == 0) ? em[jo] : NEGV;

    int buf = 0;
    sh[buf][i + 2] = make_float4(be, se, bo, so);
    __syncthreads();

#define PAIR_BODY(e1b, e1o, e1p, e2b, e2o)                                   \
    {                                                                        \
        float4 n1 = sh[buf][i + 1];                                          \
        float4 n2 = sh[buf][i];                                              \
        float mR1, sR1; LAE(n1.z, n1.w, n1.x, n1.y, mR1, sR1);               \
        float bzR = skipP ? n2.z : NEGV, wzR = skipP ? n2.w : 0.f;           \
        float mRP, sP;  LAE(mR1, sR1, bzR, wzR, mRP, sP);                    \
        float bP = __fadd_rn(mRP, (e1p));                                    \
        float mA, sA; LAE(be, se, n1.z, n1.w, mA, sA);                       \
        float m1, s1; LAE(bo, so, be, se, m1, s1);                           \
        float bzB = skip ? n1.z : NEGV, wzB = skip ? n1.w : 0.f;             \
        float mC, sC; LAE(m1, s1, bzB, wzB, mC, sC);                         \
        float be1 = __fadd_rn(mA, (e1b)), se1 = sA;                          \
        float bo1 = __fadd_rn(mC, (e1o)), so1 = sC;                          \
        float mD, sD; LAE(be1, se1, bP, sP, mD, sD);                         \
        float mE, sE; LAE(bo1, so1, be1, se1, mE, sE);                       \
        float bzF = skip ? bP : NEGV, wzF = skip ? sP : 0.f;                 \
        float mF, sF; LAE(mE, sE, bzF, wzF, mF, sF);                         \
        be = __fadd_rn(mD, (e2b)); se = sD;                                  \
        bo = __fadd_rn(mF, (e2o)); so = sF;                                  \
    }

    int ts = 0;
    if (last & 1) {                      // one plain step so pairs align
        float4 n1 = sh[buf][i + 1];
        const float* p = em + EP;        // t = 1
        float e_b = p[0];
        float e_o = p[jo];
        float mA, sA; LAE(be, se, n1.z, n1.w, mA, sA);
        float m1, s1; LAE(bo, so, be, se, m1, s1);
        float bz = skip ? n1.z : NEGV, wz = skip ? n1.w : 0.f;
        float mC, sC; LAE(m1, s1, bz, wz, mC, sC);
        be = __fadd_rn(mA, e_b); se = sA;
        bo = __fadd_rn(mC, e_o); so = sC;
        ts = 1;
        buf ^= 1;
        sh[buf][i + 2] = make_float4(be, se, bo, so);
        __syncthreads();
    }
    const int npairs = (last - ts) >> 1;
    const int nmain  = npairs & ~(DP - 1);

    // Register prefetch rings (literal indices only).
    float r1b[DP], r1o[DP], r1p[DP], r2b[DP], r2o[DP];
#pragma unroll
    for (int k = 0; k < DP; ++k) {
        const float* p1 = em + (size_t)(ts + 2 * k + 1) * EP;
        r1b[k] = p1[0];  r1o[k] = p1[jo];      r1p[k] = p1[jp];
        r2b[k] = p1[EP]; r2o[k] = p1[EP + jo];
    }

    for (int pg = 0; pg < nmain; pg += DP) {
        // Confirm the pipelined chunk (value issued a full group ago).
        if (pfc >= 0) {
            if (pfv == 0)
                while (ld_acq(&g_flag[pfc * Bb + b]) == 0) {}
            nextc = pfc;
            pfc = (nextc < maxc) ? nextc + 1 : -1;
            if (pfc >= 0) pfv = ld_acq(&g_flag[pfc * Bb + b]);
        }
#pragma unroll
        for (int k = 0; k < DP; ++k) {
            const int p = pg + k;
            const float e1b = r1b[k], e1o = r1o[k], e1p = r1p[k];
            const float e2b = r2b[k], e2o = r2o[k];
            int q = p + DP; if (q >= npairs) q = npairs - 1;
            const float* pp1 = em + (size_t)(ts + 2 * q + 1) * EP;
            r1b[k] = pp1[0];  r1o[k] = pp1[jo];      r1p[k] = pp1[jp];
            r2b[k] = pp1[EP]; r2o[k] = pp1[EP + jo];

            PAIR_BODY(e1b, e1o, e1p, e2b, e2o);

            if ((p & 15) == 15) {        // fold every 32 steps
                be = fmaxf(be + lg2f(se), NEGV); se = 1.f;
                bo = fmaxf(bo + lg2f(so), NEGV); so = 1.f;
            }
            buf ^= 1;
            sh[buf][i + 2] = make_float4(be, se, bo, so);
            __syncthreads();
        }
    }

    // Safety: confirm any chunks not yet verified (normally a no-op).
    for (int c = nextc + 1; c <= maxc; ++c)
        while (ld_acq(&g_flag[c * Bb + b]) == 0) {}

    // Remainder pairs (<=3): ring-free.
    for (int p = nmain; p < npairs; ++p) {
        const float* p1 = em + (size_t)(ts + 2 * p + 1) * EP;
        float e1b = p1[0],  e1o = p1[jo], e1p = p1[jp];
        float e2b = p1[EP], e2o = p1[EP + jo];
        PAIR_BODY(e1b, e1o, e1p, e2b, e2o);
        buf ^= 1;
        sh[buf][i + 2] = make_float4(be, se, bo, so);
        __syncthreads();
    }

    // Final fold + publish.
    be = fmaxf(be + lg2f(se), NEGV);
    bo = fmaxf(bo + lg2f(so), NEGV);
    buf ^= 1;
    sh[buf][i + 2] = make_float4(be, 1.f, bo, 1.f);
    __syncthreads();

    if (i == 0) {
        int Lb = tlen[b];
        float x = sh[buf][Lb + 2].x;     // even state 2Lb
        float y = sh[buf][Lb + 1].z;     // odd  state 2Lb-1
        float m = fmaxf(x, y);
        g_tot[b] = LN2 * (m + lg2f(ex2f(x - m) + ex2f(y - m)));
        __threadfence();
        unsigned v = atomicAdd(&g_done, 1u);
        s_lastflag = (v == Bb - 1u) ? 1 : 0;
    }
    __syncthreads();

    if (s_lastflag && i < 32) {          // last alpha block: fused reduction
        __threadfence();
        float tot = g_tot[i];
        float il  = (float)ilen[i];
        bool  ok  = tot > NEGV * 0.5f;
        float tsum = ok ? tot : 0.f;
        float tf   = ok ? il  : 0.f;
        float af   = il;
#pragma unroll
        for (int s = 16; s >= 1; s >>= 1) {
            tsum += __shfl_down_sync(0xFFFFFFFFu, tsum, s);
            tf   += __shfl_down_sync(0xFFFFFFFFu, tf, s);
            af   += __shfl_down_sync(0xFFFFFFFFu, af, s);
        }
        if (i == 0) {
            out[0] = tsum; out[1] = tf; out[2] = af;
            g_done = 0;
        }
    }
}

// ---------------------------------------------------------------------------
extern "C" void kernel_launch(void* const* d_in, const int* in_sizes, int n_in,
                              void* d_out, int out_size) {
    const float* lp      = (const float*)d_in[0];  // nnet_output [B,T,C] f32
    const int*   targets = (const int*)  d_in[1];  // [B,L] i32
    const int*   ilen    = (const int*)  d_in[2];  // [B] i32
    const int*   tlen    = (const int*)  d_in[3];  // [B] i32

    reset_kernel<<<(NGATHER + 255) / 256, 256>>>();
    ctc_main<<<Bb + NGATHER, NTHR>>>(lp, targets, ilen, tlen, (float*)d_out);
}